// round 13
// baseline (speedup 1.0000x reference)
#include <cuda_runtime.h>
#include <cstdint>

// ---------------- static device scratch (zero-initialized at load) -----------
// 1 bit per output element; 1<<21 words = 8 MB -> supports numel <= 2^26.
// NEVER cleared. Bits are set ONLY at genuine fault indices (constant across
// graph replays); marks are idempotent. The bitmap is a pure performance hint
// (per-line L2 policy choice) -- correctness never depends on it (the
// range-scatter always runs after each chunk's copy).
#define BM_WORDS (1 << 21)
__device__ unsigned g_bitmap[BM_WORDS];

#define NCHUNKS 8

// ---------------- stream/event infra (static init, before harness baseline) --
static cudaStream_t g_s2 = nullptr;
static cudaEvent_t  g_fork = nullptr, g_done = nullptr;
static cudaEvent_t  g_evCopy[NCHUNKS];
namespace {
struct StreamInit {
    StreamInit() {
        if (cudaStreamCreateWithFlags(&g_s2, cudaStreamNonBlocking) != cudaSuccess) {
            g_s2 = nullptr; return;
        }
        cudaEventCreateWithFlags(&g_fork, cudaEventDisableTiming);
        cudaEventCreateWithFlags(&g_done, cudaEventDisableTiming);
        for (int i = 0; i < NCHUNKS; i++)
            cudaEventCreateWithFlags(&g_evCopy[i], cudaEventDisableTiming);
    }
};
static StreamInit g_stream_init;
}

// ---------------- mark fault bits (idempotent, perf hint only) ---------------
__global__ void mark_kernel(const int* __restrict__ idx, int n) {
    int t = blockIdx.x * blockDim.x + threadIdx.x;
    int nvec = n >> 2;
    if (t < nvec) {
        int4 d4 = reinterpret_cast<const int4*>(idx)[t];
        atomicOr(&g_bitmap[d4.x >> 5], 1u << (d4.x & 31));
        atomicOr(&g_bitmap[d4.y >> 5], 1u << (d4.y & 31));
        atomicOr(&g_bitmap[d4.z >> 5], 1u << (d4.z & 31));
        atomicOr(&g_bitmap[d4.w >> 5], 1u << (d4.w & 31));
    } else {
        int i = (nvec << 2) + (t - nvec);
        if (i < n) {
            int d = idx[i];
            atomicOr(&g_bitmap[d >> 5], 1u << (d & 31));
        }
    }
}

// ---------------- chunked copy, branch-free per-line L2 policy ---------------
// Full lines always written (scatter overwrites fault lanes afterwards).
// Clean line -> evict_first (stream self-evicts); fault line -> evict_last
// (survives in L2 until this chunk's scatter hits it). MLP=8 front-batched.
__global__ void __launch_bounds__(256)
masked_copy_chunk(const float* __restrict__ x, float* __restrict__ out,
                  int baseVec4, int endVec4) {
    const float4* xs = reinterpret_cast<const float4*>(x);
    float4*       os = reinterpret_cast<float4*>(out);

    unsigned long long pol_stream, pol_keep;
    asm("createpolicy.fractional.L2::evict_first.b64 %0, 1.0;" : "=l"(pol_stream));
    asm("createpolicy.fractional.L2::evict_last.b64  %0, 1.0;" : "=l"(pol_keep));

    int t0 = baseVec4 + blockIdx.x * 1024 + threadIdx.x;

    if (t0 + 768 < endVec4) {
        float4 v0 = __ldcs(xs + t0);
        float4 v1 = __ldcs(xs + t0 + 256);
        float4 v2 = __ldcs(xs + t0 + 512);
        float4 v3 = __ldcs(xs + t0 + 768);
        unsigned w0 = g_bitmap[(t0)       >> 3];
        unsigned w1 = g_bitmap[(t0 + 256) >> 3];
        unsigned w2 = g_bitmap[(t0 + 512) >> 3];
        unsigned w3 = g_bitmap[(t0 + 768) >> 3];
        unsigned long long p0 = (w0 == 0u) ? pol_stream : pol_keep;
        unsigned long long p1 = (w1 == 0u) ? pol_stream : pol_keep;
        unsigned long long p2 = (w2 == 0u) ? pol_stream : pol_keep;
        unsigned long long p3 = (w3 == 0u) ? pol_stream : pol_keep;
        asm volatile("st.global.L2::cache_hint.v4.f32 [%0], {%1,%2,%3,%4}, %5;"
                     :: "l"(os + t0),       "f"(v0.x), "f"(v0.y), "f"(v0.z), "f"(v0.w), "l"(p0) : "memory");
        asm volatile("st.global.L2::cache_hint.v4.f32 [%0], {%1,%2,%3,%4}, %5;"
                     :: "l"(os + t0 + 256), "f"(v1.x), "f"(v1.y), "f"(v1.z), "f"(v1.w), "l"(p1) : "memory");
        asm volatile("st.global.L2::cache_hint.v4.f32 [%0], {%1,%2,%3,%4}, %5;"
                     :: "l"(os + t0 + 512), "f"(v2.x), "f"(v2.y), "f"(v2.z), "f"(v2.w), "l"(p2) : "memory");
        asm volatile("st.global.L2::cache_hint.v4.f32 [%0], {%1,%2,%3,%4}, %5;"
                     :: "l"(os + t0 + 768), "f"(v3.x), "f"(v3.y), "f"(v3.z), "f"(v3.w), "l"(p3) : "memory");
    } else {
        #pragma unroll
        for (int k = 0; k < 4; k++) {
            int t = t0 + k * 256;
            if (t < endVec4) {
                float4 v = __ldcs(xs + t);
                if (g_bitmap[t >> 3] == 0u) __stcs(os + t, v);
                else                        os[t] = v;
            }
        }
    }
}

// ---------------- range-filtered scatter (L2-hit writes) ---------------------
// Scans all indices (idx is 2.7MB, L2-resident after first pass) and writes
// only faults in [lo, hi) -- lines kept evict_last by this chunk's copy.
__global__ void scatter_range_kernel(const float* __restrict__ vals,
                                     const int*   __restrict__ idx,
                                     float* __restrict__ out,
                                     int n, int lo, int hi) {
    int t = blockIdx.x * blockDim.x + threadIdx.x;
    int nvec = n >> 2;
    if (t < nvec) {
        int4 d4 = reinterpret_cast<const int4*>(idx)[t];
        int base = t << 2;
        if (d4.x >= lo && d4.x < hi) out[d4.x] = vals[base + 0];
        if (d4.y >= lo && d4.y < hi) out[d4.y] = vals[base + 1];
        if (d4.z >= lo && d4.z < hi) out[d4.z] = vals[base + 2];
        if (d4.w >= lo && d4.w < hi) out[d4.w] = vals[base + 3];
    } else if (t == nvec) {
        for (int i = nvec << 2; i < n; i++) {
            int d = idx[i];
            if (d >= lo && d < hi) out[d] = vals[i];
        }
    }
}

// ---------------- fallback: serial copy + scatter ----------------------------
__global__ void scatter_all_kernel(const float* __restrict__ vals,
                                   const int* __restrict__ idx,
                                   float* __restrict__ out, int n) {
    int i = blockIdx.x * blockDim.x + threadIdx.x;
    if (i < n) out[idx[i]] = vals[i];
}

extern "C" void kernel_launch(void* const* d_in, const int* in_sizes, int n_in,
                              void* d_out, int out_size) {
    const float* x          = (const float*)d_in[0];
    const float* fault_vals = (const float*)d_in[1];
    const int*   fault_idx  = (const int*)d_in[2];
    float* out = (float*)d_out;

    const int numel   = in_sizes[0];   // 67,108,864
    const int covered = in_sizes[1];   // 671,089

    if ((long long)numel > (long long)BM_WORDS * 32 || (numel & 3) != 0 ||
        !g_s2 || covered == 0) {
        cudaMemcpyAsync(out, x, (size_t)numel * sizeof(float),
                        cudaMemcpyDeviceToDevice, 0);
        if (covered > 0)
            scatter_all_kernel<<<(covered + 255) / 256, 256>>>(
                fault_vals, fault_idx, out, covered);
        return;
    }

    const int nvec4     = numel >> 2;
    const int chunkVec4 = (nvec4 + NCHUNKS - 1) / NCHUNKS;
    const int mthreads  = (covered >> 2) + (covered & 3) + 1;
    const int mblocks   = (mthreads + 255) / 256;
    const int sblocks   = ((covered >> 2) + 1 + 255) / 256;

    // s2: mark (perf-only, hidden under chunk 0's copy)
    cudaEventRecord(g_fork, 0);
    cudaStreamWaitEvent(g_s2, g_fork, 0);
    mark_kernel<<<mblocks, 256, 0, g_s2>>>(fault_idx, covered);

    // s1: copy chunk c; s2: scatter chunk c's faults (L2 hits), overlapping
    // the copy of chunk c+1 with ~no DRAM contention.
    for (int c = 0; c < NCHUNKS; c++) {
        int base = c * chunkVec4;
        int end  = base + chunkVec4; if (end > nvec4) end = nvec4;
        if (base >= end) break;

        int cblocks = (end - base + 1023) / 1024;
        masked_copy_chunk<<<cblocks, 256>>>(x, out, base, end);
        cudaEventRecord(g_evCopy[c], 0);
        cudaStreamWaitEvent(g_s2, g_evCopy[c], 0);
        scatter_range_kernel<<<sblocks, 256, 0, g_s2>>>(
            fault_vals, fault_idx, out, covered, base << 2, end << 2);
    }

    cudaEventRecord(g_done, g_s2);
    cudaStreamWaitEvent(0, g_done, 0);   // join before graph end
}